// round 15
// baseline (speedup 1.0000x reference)
#include <cuda_runtime.h>
#include <cuda_fp16.h>
#include <mma.h>
#include <cstdint>
#include <cstddef>

using namespace nvcuda;

#define NN 10000
#define NE 320000
#define FD 256
#define EDF 64

// weight offsets inside g_wh (halves)
#define OW1 0
#define OM1 (FD * FD)
#define OM2 (OM1 + 576 * FD)
#define OW2 (OM2 + 576 * FD)
#define WTOT (OW2 + FD * FD)

// ---------------- scratch ----------------
__device__ float  g_h0[NN * FD];
__device__ __half g_h0h[NN * FD];
__device__ __half g_Xsh[NN * FD];
__device__ __half g_Xdh[NN * FD];
__device__ __half g_xh[NN * FD];
__device__ __half g_efh[(size_t)NE * EDF];
__device__ __half g_wh[WTOT];
__device__ int g_rowptr[NN + 1];
__device__ int g_cnt[NN];
__device__ int g_ofs[NN];
__device__ int g_srcs[NE];
__device__ int g_dsts[NE];
__device__ int g_eids[NE];

__device__ __forceinline__ float gelu_f(float v) {
    float u = 0.7978845608028654f * (v + 0.044715f * v * v * v);
    float t;
    asm("tanh.approx.f32 %0, %1;" : "=f"(t) : "f"(u));
    return 0.5f * v * (1.0f + t);
}

__device__ __forceinline__ void cp16(uint32_t dst, const void* src, bool p) {
    asm volatile("cp.async.ca.shared.global [%0], [%1], 16, %2;"
                 :: "r"(dst), "l"(src), "r"(p ? 16 : 0));
}
#define CP_COMMIT() asm volatile("cp.async.commit_group;")
#define CP_WAIT(n)  asm volatile("cp.async.wait_group %0;" :: "n"(n))

__device__ __forceinline__ void red_add_v4(float* ptr, float4 v) {
    asm volatile("red.global.add.v4.f32 [%0], {%1, %2, %3, %4};"
                 :: "l"(ptr), "f"(v.x), "f"(v.y), "f"(v.z), "f"(v.w) : "memory");
}

// ---------------- fp32 -> fp16 conversion + cnt zeroing in ONE launch ----------------
__global__ void convert_all(const float* __restrict__ x, const float* __restrict__ ef,
                            const float* __restrict__ wff1, const float* __restrict__ wmp1,
                            const float* __restrict__ wmp2, const float* __restrict__ wff2,
                            __half* __restrict__ xh, __half* __restrict__ efh,
                            __half* __restrict__ wh, int4* __restrict__ cnt4) {
    const int NX4 = NN * FD / 4;
    const int NE4 = NE * EDF / 4;
    const int W14 = FD * FD / 4, WM4 = 576 * FD / 4;
    const int NZ4 = NN / 4;   // cnt zero range (NN divisible by 4)
    long long i = (long long)blockIdx.x * blockDim.x + threadIdx.x;
    const float4* s;
    __half* d;
    long long j = i;
    if (j < NX4) { s = (const float4*)x; d = xh; }
    else {
        j -= NX4;
        if (j < NE4) { s = (const float4*)ef; d = efh; }
        else {
            j -= NE4;
            if (j < W14) { s = (const float4*)wff1; d = wh + OW1; }
            else {
                j -= W14;
                if (j < WM4) { s = (const float4*)wmp1; d = wh + OM1; }
                else {
                    j -= WM4;
                    if (j < WM4) { s = (const float4*)wmp2; d = wh + OM2; }
                    else {
                        j -= WM4;
                        if (j < W14) { s = (const float4*)wff2; d = wh + OW2; }
                        else {
                            j -= W14;
                            if (j < NZ4) cnt4[j] = make_int4(0, 0, 0, 0);
                            return;
                        }
                    }
                }
            }
        }
    }
    float4 v = s[j];
    __half2* dd = (__half2*)(d + j * 4);
    dd[0] = __floats2half2_rn(v.x, v.y);
    dd[1] = __floats2half2_rn(v.z, v.w);
}

// h0 (fp32, post-atomics) -> h0h (half)
__global__ void cvt_h0(const float4* __restrict__ a, __half2* __restrict__ b, int n4) {
    int i = blockIdx.x * blockDim.x + threadIdx.x;
    if (i < n4) {
        float4 v = a[i];
        b[i * 2]     = __floats2half2_rn(v.x, v.y);
        b[i * 2 + 1] = __floats2half2_rn(v.z, v.w);
    }
}

// ---------------- CSR construction ----------------
__global__ void hist_kernel(const int* __restrict__ ei, int* __restrict__ cnt, int E) {
    int e = blockIdx.x * blockDim.x + threadIdx.x;
    if (e < E) atomicAdd(&cnt[ei[E + e]], 1);
}

__global__ void scan_kernel(const int* __restrict__ cnt, int* __restrict__ rowptr,
                            int* __restrict__ ofs, int n) {
    __shared__ int part[1024];
    const int PER = 16;
    int t = threadIdx.x;
    int base = t * PER;
    int local[PER];
    int s = 0;
#pragma unroll
    for (int j = 0; j < PER; j++) {
        int idx = base + j;
        int c = (idx < n) ? cnt[idx] : 0;
        local[j] = s;
        s += c;
    }
    part[t] = s;
    __syncthreads();
    for (int off = 1; off < 1024; off <<= 1) {
        int v = (t >= off) ? part[t - off] : 0;
        __syncthreads();
        part[t] += v;
        __syncthreads();
    }
    int pre = (t > 0) ? part[t - 1] : 0;
#pragma unroll
    for (int j = 0; j < PER; j++) {
        int idx = base + j;
        if (idx < n) {
            int v = pre + local[j];
            rowptr[idx] = v;
            ofs[idx] = v;
        }
    }
    if (t == 1023) rowptr[n] = part[1023];
}

__global__ void scatter_kernel(const int* __restrict__ ei, int* __restrict__ ofs,
                               int* __restrict__ srcs, int* __restrict__ dsts,
                               int* __restrict__ eids, int E) {
    int e = blockIdx.x * blockDim.x + threadIdx.x;
    if (e < E) {
        int d = ei[E + e];
        int p = atomicAdd(&ofs[d], 1);
        srcs[p] = ei[e];
        dsts[p] = d;
        eids[p] = e;
    }
}

// ---------------- node GEMM: fp16 in, fp32 acc, cp.async 2-stage ----------------
__global__ void __launch_bounds__(256) gemm_node(
    const __half* __restrict__ A,
    const __half* __restrict__ B0, const __half* __restrict__ B1,
    const float* __restrict__ bias,
    const float* __restrict__ resid,
    float* __restrict__ C0f, float* __restrict__ C1f,
    __half* __restrict__ C0h, __half* __restrict__ C1h,
    int M, int dogelu)
{
    constexpr int BM = 128, BN = 64, BK = 32;
    constexpr int LDA = 40, LDB = 72;
    constexpr int STG = BM * LDA + BK * LDB;
    __shared__ __align__(16) char smraw[BM * BN * 4];
    __half* sm = (__half*)smraw;
    float* Cs = (float*)smraw;

    int tid = threadIdx.x;
    int warp = tid >> 5;
    int wm = warp >> 1, wn = warp & 1;
    int bm = blockIdx.x * BM;
    int sel = blockIdx.y >> 2;
    int cg = blockIdx.y & 3;
    const __half* B = sel ? B1 : B0;
    float* Cf = sel ? C1f : C0f;
    __half* Ch = sel ? C1h : C0h;
    int bn = cg * BN;

    auto issue = [&](int st, int k0) {
        __half* As = sm + st * STG;
        __half* Bs = As + BM * LDA;
#pragma unroll
        for (int p = 0; p < 2; p++) {
            int j = tid + 256 * p;
            int row = j >> 2, ch = j & 3;
            int grow = bm + row;
            cp16((uint32_t)__cvta_generic_to_shared(As + row * LDA + ch * 8),
                 A + (size_t)grow * FD + k0 + ch * 8, grow < M);
        }
        {
            int row = tid >> 3, ch = tid & 7;
            cp16((uint32_t)__cvta_generic_to_shared(Bs + row * LDB + ch * 8),
                 B + (size_t)(k0 + row) * FD + bn + ch * 8, true);
        }
    };

    wmma::fragment<wmma::accumulator, 16, 16, 16, float> acc[2][2];
#pragma unroll
    for (int i = 0; i < 2; i++)
#pragma unroll
        for (int j = 0; j < 2; j++) wmma::fill_fragment(acc[i][j], 0.0f);

    issue(0, 0);
    CP_COMMIT();

    constexpr int NIT = FD / BK;  // 8
#pragma unroll 1
    for (int it = 0; it < NIT; it++) {
        if (it + 1 < NIT) {
            issue((it + 1) & 1, (it + 1) * BK);
            CP_COMMIT();
            CP_WAIT(1);
        } else {
            CP_WAIT(0);
        }
        __syncthreads();
        __half* As = sm + (it & 1) * STG;
        __half* Bs = As + BM * LDA;
#pragma unroll
        for (int kk = 0; kk < BK; kk += 16) {
            wmma::fragment<wmma::matrix_a, 16, 16, 16, __half, wmma::row_major> a[2];
            wmma::fragment<wmma::matrix_b, 16, 16, 16, __half, wmma::row_major> b[2];
#pragma unroll
            for (int i = 0; i < 2; i++)
                wmma::load_matrix_sync(a[i], As + (wm * 32 + i * 16) * LDA + kk, LDA);
#pragma unroll
            for (int j = 0; j < 2; j++)
                wmma::load_matrix_sync(b[j], Bs + kk * LDB + wn * 32 + j * 16, LDB);
#pragma unroll
            for (int i = 0; i < 2; i++)
#pragma unroll
                for (int j = 0; j < 2; j++)
                    wmma::mma_sync(acc[i][j], a[i], b[j], acc[i][j]);
        }
        __syncthreads();
    }

#pragma unroll
    for (int i = 0; i < 2; i++)
#pragma unroll
        for (int j = 0; j < 2; j++)
            wmma::store_matrix_sync(Cs + (wm * 32 + i * 16) * BN + wn * 32 + j * 16,
                                    acc[i][j], BN, wmma::mem_row_major);
    __syncthreads();
    for (int idx = tid; idx < BM * BN; idx += 256) {
        int r = idx >> 6, c = idx & 63;
        int grow = bm + r;
        if (grow >= M) continue;
        float v = Cs[idx];
        if (bias) v += bias[bn + c];
        if (dogelu) v = gelu_f(v);
        if (resid) v += resid[(size_t)grow * FD + bn + c];
        if (Cf) Cf[(size_t)grow * FD + bn + c] = v;
        if (Ch) Ch[(size_t)grow * FD + bn + c] = __float2half(v);
    }
}

// ---------------- dst-sorted fused edge kernel (fp16 MMA, segment-reduced epilogue) ----------------
// grid = (4, chunks): blockIdx.x = column group, blockIdx.y = 128-edge chunk (dst-sorted order).
__global__ void __launch_bounds__(256, 5) edge_sorted(
    const __half* __restrict__ ef,
    const __half* __restrict__ Wef,   // [64, 256] half
    const float* __restrict__ bias,
    const __half* __restrict__ Xs, const __half* __restrict__ Xd,
    float* __restrict__ out,          // updated in place: out[dst] += gelu(...)
    int E)
{
    constexpr int CH = 128, LDA = 72, LDB = 72, LDC = 68;
    __shared__ __align__(16) char smraw[CH * LDC * 4];
    __half* Aef = (__half*)smraw;
    __half* Wb  = Aef + CH * LDA;
    float*  Cs  = (float*)smraw;
    __shared__ int s_src[CH], s_dst[CH], s_eid[CH];

    int tid = threadIdx.x;
    int cg = blockIdx.x;
    int base = blockIdx.y * CH;
    int warp = tid >> 5;
    int wm = warp >> 1, wn = warp & 1;

    if (tid < CH) {
        int i = base + tid;
        bool v = i < E;
        s_eid[tid] = v ? g_eids[i] : -1;
        s_src[tid] = v ? g_srcs[i] : 0;
        s_dst[tid] = v ? g_dsts[i] : -1;
    }
    __syncthreads();

    // gather ef rows (128B each, 8 chunks/row) by sorted eid
#pragma unroll
    for (int p = 0; p < 4; p++) {
        int j = tid + 256 * p;
        int row = j >> 3, ch = j & 7;
        int e = s_eid[row];
        cp16((uint32_t)__cvta_generic_to_shared(Aef + row * LDA + ch * 8),
             ef + (size_t)(e < 0 ? 0 : e) * EDF + ch * 8, e >= 0);
    }
    // Wef tile (64x64, L2-resident)
#pragma unroll
    for (int p = 0; p < 2; p++) {
        int j = tid + 256 * p;
        int row = j >> 3, ch = j & 7;
        cp16((uint32_t)__cvta_generic_to_shared(Wb + row * LDB + ch * 8),
             Wef + (size_t)row * FD + cg * 64 + ch * 8, true);
    }
    CP_COMMIT();
    CP_WAIT(0);
    __syncthreads();

    wmma::fragment<wmma::accumulator, 16, 16, 16, float> acc[2][2];
#pragma unroll
    for (int i = 0; i < 2; i++)
#pragma unroll
        for (int j = 0; j < 2; j++) wmma::fill_fragment(acc[i][j], 0.0f);

#pragma unroll
    for (int kk = 0; kk < EDF; kk += 16) {
        wmma::fragment<wmma::matrix_a, 16, 16, 16, __half, wmma::row_major> a[2];
        wmma::fragment<wmma::matrix_b, 16, 16, 16, __half, wmma::row_major> b[2];
#pragma unroll
        for (int i = 0; i < 2; i++)
            wmma::load_matrix_sync(a[i], Aef + (wm * 32 + i * 16) * LDA + kk, LDA);
#pragma unroll
        for (int j = 0; j < 2; j++)
            wmma::load_matrix_sync(b[j], Wb + kk * LDB + wn * 32 + j * 16, LDB);
#pragma unroll
        for (int i = 0; i < 2; i++)
#pragma unroll
            for (int j = 0; j < 2; j++)
                wmma::mma_sync(acc[i][j], a[i], b[j], acc[i][j]);
    }
    __syncthreads();  // Aef + Wb reads done -> safe to overwrite with fp32 C

#pragma unroll
    for (int i = 0; i < 2; i++)
#pragma unroll
        for (int j = 0; j < 2; j++)
            wmma::store_matrix_sync(Cs + (wm * 32 + i * 16) * LDC + wn * 32 + j * 16,
                                    acc[i][j], LDC, wmma::mem_row_major);
    __syncthreads();

    // epilogue: thread owns 4 cols x 8 consecutive rows; dsts sorted -> segment accumulate,
    // one Xd load + one red.v4 per segment.
    int c4 = tid & 15;
    int rr = tid >> 4;
    const float4 bv4 = *(const float4*)(bias + cg * 64 + c4 * 4);
    float4 accv = make_float4(0.f, 0.f, 0.f, 0.f);
    float4 xd4 = make_float4(0.f, 0.f, 0.f, 0.f);
    int prev = -1;
#pragma unroll
    for (int it = 0; it < 8; it++) {
        int row = rr * 8 + it;
        int d = s_dst[row];
        if (d < 0) break;
        if (d != prev) {
            if (prev >= 0)
                red_add_v4(out + (size_t)prev * FD + cg * 64 + c4 * 4, accv);
            prev = d;
            accv = make_float4(0.f, 0.f, 0.f, 0.f);
            const __half2* xdp = (const __half2*)(Xd + (size_t)d * FD + cg * 64 + c4 * 4);
            float2 a01 = __half22float2(xdp[0]);
            float2 a23 = __half22float2(xdp[1]);
            xd4 = make_float4(a01.x, a01.y, a23.x, a23.y);
        }
        const __half2* xsp = (const __half2*)(Xs + (size_t)s_src[row] * FD + cg * 64 + c4 * 4);
        float2 s01 = __half22float2(xsp[0]);
        float2 s23 = __half22float2(xsp[1]);
        float4 cv = *(float4*)(Cs + row * LDC + c4 * 4);
        accv.x += gelu_f(cv.x + bv4.x + s01.x + xd4.x);
        accv.y += gelu_f(cv.y + bv4.y + s01.y + xd4.y);
        accv.z += gelu_f(cv.z + bv4.z + s23.x + xd4.z);
        accv.w += gelu_f(cv.w + bv4.w + s23.y + xd4.w);
    }
    if (prev >= 0)
        red_add_v4(out + (size_t)prev * FD + cg * 64 + c4 * 4, accv);
}

// ---------------- launch ----------------
extern "C" void kernel_launch(void* const* d_in, const int* in_sizes, int n_in,
                              void* d_out, int out_size) {
    const float* x    = (const float*)d_in[0];
    const int* ei     = (const int*)d_in[1];   // int32 (JAX x64 disabled)
    const float* ef   = (const float*)d_in[2];
    const float* Wff1 = (const float*)d_in[3];
    const float* bff1 = (const float*)d_in[4];
    const float* Wmp1 = (const float*)d_in[5];
    const float* bmp1 = (const float*)d_in[6];
    const float* Wmp2 = (const float*)d_in[7];
    const float* bmp2 = (const float*)d_in[8];
    const float* Wff2 = (const float*)d_in[9];
    const float* bff2 = (const float*)d_in[10];

    int N = in_sizes[0] / FD;
    int E = in_sizes[1] / 2;

    float* h0;
    __half *h0h, *Xsh, *Xdh, *xh, *efh, *wh;
    int *rowptr, *cnt, *ofs, *srcs, *dsts, *eids;
    cudaGetSymbolAddress((void**)&h0, g_h0);
    cudaGetSymbolAddress((void**)&h0h, g_h0h);
    cudaGetSymbolAddress((void**)&Xsh, g_Xsh);
    cudaGetSymbolAddress((void**)&Xdh, g_Xdh);
    cudaGetSymbolAddress((void**)&xh, g_xh);
    cudaGetSymbolAddress((void**)&efh, g_efh);
    cudaGetSymbolAddress((void**)&wh, g_wh);
    cudaGetSymbolAddress((void**)&rowptr, g_rowptr);
    cudaGetSymbolAddress((void**)&cnt, g_cnt);
    cudaGetSymbolAddress((void**)&ofs, g_ofs);
    cudaGetSymbolAddress((void**)&srcs, g_srcs);
    cudaGetSymbolAddress((void**)&dsts, g_dsts);
    cudaGetSymbolAddress((void**)&eids, g_eids);

    dim3 thr(256);
    int eb = (E + 255) / 256;
    int n4 = N * FD / 4;
    long long tot4 = (long long)N * FD / 4 + (long long)E * EDF / 4 + WTOT / 4 + NN / 4;

    dim3 gN((N + 127) / 128, 4);
    dim3 gN2((N + 127) / 128, 8);
    dim3 gE(4, (E + 127) / 128);

    // 1: convert inputs/weights to fp16 + zero CSR counts
    convert_all<<<(int)((tot4 + 255) / 256), thr>>>(x, ef, Wff1, Wmp1, Wmp2, Wff2,
                                                    xh, efh, wh, (int4*)cnt);
    // 2: CSR histogram
    hist_kernel<<<eb, thr>>>(ei, cnt, E);
    // 3: FFN1 -> h0 (fp32) + h0h (half)
    gemm_node<<<gN, thr>>>(xh, wh + OW1, nullptr, bff1, nullptr, h0, nullptr, h0h, nullptr, N, 1);
    // 4: dual1 (ncu PROBE) -> Xsh, Xdh
    gemm_node<<<gN2, thr>>>(h0h, wh + OM1, wh + OM1 + FD * FD, nullptr, nullptr,
                            nullptr, nullptr, Xsh, Xdh, N, 0);
    // 5-6: finish CSR
    scan_kernel<<<1, 1024>>>(cnt, rowptr, ofs, N);
    scatter_kernel<<<eb, thr>>>(ei, ofs, srcs, dsts, eids, E);
    // 7: edge1: h0 += agg1 (fp32 atomics, in place)
    edge_sorted<<<gE, thr>>>(efh, wh + OM1 + 2 * FD * FD, bmp1, Xsh, Xdh, h0, E);
    // 8: h0 -> h0h
    cvt_h0<<<(n4 + 255) / 256, thr>>>((const float4*)h0, (__half2*)h0h, n4);
    // 9: dual2 -> Xsh, Xdh
    gemm_node<<<gN2, thr>>>(h0h, wh + OM2, wh + OM2 + FD * FD, nullptr, nullptr,
                            nullptr, nullptr, Xsh, Xdh, N, 0);
    // 10: edge2: h0 += agg2 (in place)
    edge_sorted<<<gE, thr>>>(efh, wh + OM2 + 2 * FD * FD, bmp2, Xsh, Xdh, h0, E);
    // 11: h0 -> h0h
    cvt_h0<<<(n4 + 255) / 256, thr>>>((const float4*)h0, (__half2*)h0h, n4);
    // 12: FFN2 + residual -> out
    gemm_node<<<gN, thr>>>(h0h, wh + OW2, nullptr, bff2, x, (float*)d_out, nullptr,
                           nullptr, nullptr, N, 0);
}

// round 16
// speedup vs baseline: 1.3336x; 1.3336x over previous
#include <cuda_runtime.h>
#include <cuda_fp16.h>
#include <mma.h>
#include <cstdint>
#include <cstddef>

using namespace nvcuda;

#define NN 10000
#define NE 320000
#define FD 256
#define EDF 64

// weight offsets inside g_wh (halves)
#define OW1 0
#define OM1 (FD * FD)
#define OM2 (OM1 + 576 * FD)
#define OW2 (OM2 + 576 * FD)
#define WTOT (OW2 + FD * FD)

// ---------------- scratch ----------------
__device__ float  g_h0[NN * FD];
__device__ __half g_h0h[NN * FD];
__device__ __half g_Xsh[NN * FD];
__device__ __half g_Xdh[NN * FD];
__device__ __half g_xh[NN * FD];
__device__ __half g_efh[(size_t)NE * EDF];
__device__ __half g_wh[WTOT];
__device__ int g_rowptr[NN + 1];
__device__ int g_cnt[NN];
__device__ int g_ofs[NN];
__device__ int g_srcs[NE];
__device__ int g_dsts[NE];
__device__ int g_eids[NE];

__device__ __forceinline__ float gelu_f(float v) {
    float u = 0.7978845608028654f * (v + 0.044715f * v * v * v);
    float t;
    asm("tanh.approx.f32 %0, %1;" : "=f"(t) : "f"(u));
    return 0.5f * v * (1.0f + t);
}

__device__ __forceinline__ void cp16(uint32_t dst, const void* src, bool p) {
    asm volatile("cp.async.ca.shared.global [%0], [%1], 16, %2;"
                 :: "r"(dst), "l"(src), "r"(p ? 16 : 0));
}
#define CP_COMMIT() asm volatile("cp.async.commit_group;")
#define CP_WAIT(n)  asm volatile("cp.async.wait_group %0;" :: "n"(n))

__device__ __forceinline__ void red_add_v4(float* ptr, float4 v) {
    asm volatile("red.global.add.v4.f32 [%0], {%1, %2, %3, %4};"
                 :: "l"(ptr), "f"(v.x), "f"(v.y), "f"(v.z), "f"(v.w) : "memory");
}

// ---------------- fp32 -> fp16 conversion + cnt zeroing in ONE launch ----------------
__global__ void convert_all(const float* __restrict__ x, const float* __restrict__ ef,
                            const float* __restrict__ wff1, const float* __restrict__ wmp1,
                            const float* __restrict__ wmp2, const float* __restrict__ wff2,
                            __half* __restrict__ xh, __half* __restrict__ efh,
                            __half* __restrict__ wh, int4* __restrict__ cnt4) {
    const int NX4 = NN * FD / 4;
    const int NE4 = NE * EDF / 4;
    const int W14 = FD * FD / 4, WM4 = 576 * FD / 4;
    const int NZ4 = NN / 4;
    long long i = (long long)blockIdx.x * blockDim.x + threadIdx.x;
    const float4* s;
    __half* d;
    long long j = i;
    if (j < NX4) { s = (const float4*)x; d = xh; }
    else {
        j -= NX4;
        if (j < NE4) { s = (const float4*)ef; d = efh; }
        else {
            j -= NE4;
            if (j < W14) { s = (const float4*)wff1; d = wh + OW1; }
            else {
                j -= W14;
                if (j < WM4) { s = (const float4*)wmp1; d = wh + OM1; }
                else {
                    j -= WM4;
                    if (j < WM4) { s = (const float4*)wmp2; d = wh + OM2; }
                    else {
                        j -= WM4;
                        if (j < W14) { s = (const float4*)wff2; d = wh + OW2; }
                        else {
                            j -= W14;
                            if (j < NZ4) cnt4[j] = make_int4(0, 0, 0, 0);
                            return;
                        }
                    }
                }
            }
        }
    }
    float4 v = s[j];
    __half2* dd = (__half2*)(d + j * 4);
    dd[0] = __floats2half2_rn(v.x, v.y);
    dd[1] = __floats2half2_rn(v.z, v.w);
}

// h0 (fp32, post-atomics) -> h0h (half)
__global__ void cvt_h0(const float4* __restrict__ a, __half2* __restrict__ b, int n4) {
    int i = blockIdx.x * blockDim.x + threadIdx.x;
    if (i < n4) {
        float4 v = a[i];
        b[i * 2]     = __floats2half2_rn(v.x, v.y);
        b[i * 2 + 1] = __floats2half2_rn(v.z, v.w);
    }
}

// ---------------- CSR construction ----------------
__global__ void hist_kernel(const int* __restrict__ ei, int* __restrict__ cnt, int E) {
    int e = blockIdx.x * blockDim.x + threadIdx.x;
    if (e < E) atomicAdd(&cnt[ei[E + e]], 1);
}

__global__ void scan_kernel(const int* __restrict__ cnt, int* __restrict__ rowptr,
                            int* __restrict__ ofs, int n) {
    __shared__ int part[1024];
    const int PER = 16;
    int t = threadIdx.x;
    int base = t * PER;
    int local[PER];
    int s = 0;
#pragma unroll
    for (int j = 0; j < PER; j++) {
        int idx = base + j;
        int c = (idx < n) ? cnt[idx] : 0;
        local[j] = s;
        s += c;
    }
    part[t] = s;
    __syncthreads();
    for (int off = 1; off < 1024; off <<= 1) {
        int v = (t >= off) ? part[t - off] : 0;
        __syncthreads();
        part[t] += v;
        __syncthreads();
    }
    int pre = (t > 0) ? part[t - 1] : 0;
#pragma unroll
    for (int j = 0; j < PER; j++) {
        int idx = base + j;
        if (idx < n) {
            int v = pre + local[j];
            rowptr[idx] = v;
            ofs[idx] = v;
        }
    }
    if (t == 1023) rowptr[n] = part[1023];
}

__global__ void scatter_kernel(const int* __restrict__ ei, int* __restrict__ ofs,
                               int* __restrict__ srcs, int* __restrict__ dsts,
                               int* __restrict__ eids, int E) {
    int e = blockIdx.x * blockDim.x + threadIdx.x;
    if (e < E) {
        int d = ei[E + e];
        int p = atomicAdd(&ofs[d], 1);
        srcs[p] = ei[e];
        dsts[p] = d;
        eids[p] = e;
    }
}

// ---------------- node GEMM: fp16 in, fp32 acc, cp.async 2-stage ----------------
__global__ void __launch_bounds__(256) gemm_node(
    const __half* __restrict__ A,
    const __half* __restrict__ B0, const __half* __restrict__ B1,
    const float* __restrict__ bias,
    const float* __restrict__ resid,
    float* __restrict__ C0f, float* __restrict__ C1f,
    __half* __restrict__ C0h, __half* __restrict__ C1h,
    int M, int dogelu)
{
    constexpr int BM = 128, BN = 64, BK = 32;
    constexpr int LDA = 40, LDB = 72;
    constexpr int STG = BM * LDA + BK * LDB;
    __shared__ __align__(16) char smraw[BM * BN * 4];
    __half* sm = (__half*)smraw;
    float* Cs = (float*)smraw;

    int tid = threadIdx.x;
    int warp = tid >> 5;
    int wm = warp >> 1, wn = warp & 1;
    int bm = blockIdx.x * BM;
    int sel = blockIdx.y >> 2;
    int cg = blockIdx.y & 3;
    const __half* B = sel ? B1 : B0;
    float* Cf = sel ? C1f : C0f;
    __half* Ch = sel ? C1h : C0h;
    int bn = cg * BN;

    auto issue = [&](int st, int k0) {
        __half* As = sm + st * STG;
        __half* Bs = As + BM * LDA;
#pragma unroll
        for (int p = 0; p < 2; p++) {
            int j = tid + 256 * p;
            int row = j >> 2, ch = j & 3;
            int grow = bm + row;
            cp16((uint32_t)__cvta_generic_to_shared(As + row * LDA + ch * 8),
                 A + (size_t)grow * FD + k0 + ch * 8, grow < M);
        }
        {
            int row = tid >> 3, ch = tid & 7;
            cp16((uint32_t)__cvta_generic_to_shared(Bs + row * LDB + ch * 8),
                 B + (size_t)(k0 + row) * FD + bn + ch * 8, true);
        }
    };

    wmma::fragment<wmma::accumulator, 16, 16, 16, float> acc[2][2];
#pragma unroll
    for (int i = 0; i < 2; i++)
#pragma unroll
        for (int j = 0; j < 2; j++) wmma::fill_fragment(acc[i][j], 0.0f);

    issue(0, 0);
    CP_COMMIT();

    constexpr int NIT = FD / BK;  // 8
#pragma unroll 1
    for (int it = 0; it < NIT; it++) {
        if (it + 1 < NIT) {
            issue((it + 1) & 1, (it + 1) * BK);
            CP_COMMIT();
            CP_WAIT(1);
        } else {
            CP_WAIT(0);
        }
        __syncthreads();
        __half* As = sm + (it & 1) * STG;
        __half* Bs = As + BM * LDA;
#pragma unroll
        for (int kk = 0; kk < BK; kk += 16) {
            wmma::fragment<wmma::matrix_a, 16, 16, 16, __half, wmma::row_major> a[2];
            wmma::fragment<wmma::matrix_b, 16, 16, 16, __half, wmma::row_major> b[2];
#pragma unroll
            for (int i = 0; i < 2; i++)
                wmma::load_matrix_sync(a[i], As + (wm * 32 + i * 16) * LDA + kk, LDA);
#pragma unroll
            for (int j = 0; j < 2; j++)
                wmma::load_matrix_sync(b[j], Bs + kk * LDB + wn * 32 + j * 16, LDB);
#pragma unroll
            for (int i = 0; i < 2; i++)
#pragma unroll
                for (int j = 0; j < 2; j++)
                    wmma::mma_sync(acc[i][j], a[i], b[j], acc[i][j]);
        }
        __syncthreads();
    }

#pragma unroll
    for (int i = 0; i < 2; i++)
#pragma unroll
        for (int j = 0; j < 2; j++)
            wmma::store_matrix_sync(Cs + (wm * 32 + i * 16) * BN + wn * 32 + j * 16,
                                    acc[i][j], BN, wmma::mem_row_major);
    __syncthreads();
    for (int idx = tid; idx < BM * BN; idx += 256) {
        int r = idx >> 6, c = idx & 63;
        int grow = bm + r;
        if (grow >= M) continue;
        float v = Cs[idx];
        if (bias) v += bias[bn + c];
        if (dogelu) v = gelu_f(v);
        if (resid) v += resid[(size_t)grow * FD + bn + c];
        if (Cf) Cf[(size_t)grow * FD + bn + c] = v;
        if (Ch) Ch[(size_t)grow * FD + bn + c] = __float2half(v);
    }
}

// ---------------- dst-sorted fused edge kernel (fp16 MMA, segment-reduced epilogue) ----------------
// grid = (4, chunks): blockIdx.x = column group, blockIdx.y = 128-edge chunk (dst-sorted order).
// NOTE: minCTAs=4 (R13-proven). 5 forces a 51-reg cap -> epilogue spills -> +55us/launch (R15).
__global__ void __launch_bounds__(256, 4) edge_sorted(
    const __half* __restrict__ ef,
    const __half* __restrict__ Wef,   // [64, 256] half
    const float* __restrict__ bias,
    const __half* __restrict__ Xs, const __half* __restrict__ Xd,
    float* __restrict__ out,          // updated in place: out[dst] += gelu(...)
    int E)
{
    constexpr int CH = 128, LDA = 72, LDB = 72, LDC = 68;
    __shared__ __align__(16) char smraw[CH * LDC * 4];
    __half* Aef = (__half*)smraw;
    __half* Wb  = Aef + CH * LDA;
    float*  Cs  = (float*)smraw;
    __shared__ int s_src[CH], s_dst[CH], s_eid[CH];

    int tid = threadIdx.x;
    int cg = blockIdx.x;
    int base = blockIdx.y * CH;
    int warp = tid >> 5;
    int wm = warp >> 1, wn = warp & 1;

    if (tid < CH) {
        int i = base + tid;
        bool v = i < E;
        s_eid[tid] = v ? g_eids[i] : -1;
        s_src[tid] = v ? g_srcs[i] : 0;
        s_dst[tid] = v ? g_dsts[i] : -1;
    }
    __syncthreads();

    // gather ef rows (128B each, 8 chunks/row) by sorted eid
#pragma unroll
    for (int p = 0; p < 4; p++) {
        int j = tid + 256 * p;
        int row = j >> 3, ch = j & 7;
        int e = s_eid[row];
        cp16((uint32_t)__cvta_generic_to_shared(Aef + row * LDA + ch * 8),
             ef + (size_t)(e < 0 ? 0 : e) * EDF + ch * 8, e >= 0);
    }
    // Wef tile (64x64, L2-resident)
#pragma unroll
    for (int p = 0; p < 2; p++) {
        int j = tid + 256 * p;
        int row = j >> 3, ch = j & 7;
        cp16((uint32_t)__cvta_generic_to_shared(Wb + row * LDB + ch * 8),
             Wef + (size_t)row * FD + cg * 64 + ch * 8, true);
    }
    CP_COMMIT();
    CP_WAIT(0);
    __syncthreads();

    wmma::fragment<wmma::accumulator, 16, 16, 16, float> acc[2][2];
#pragma unroll
    for (int i = 0; i < 2; i++)
#pragma unroll
        for (int j = 0; j < 2; j++) wmma::fill_fragment(acc[i][j], 0.0f);

#pragma unroll
    for (int kk = 0; kk < EDF; kk += 16) {
        wmma::fragment<wmma::matrix_a, 16, 16, 16, __half, wmma::row_major> a[2];
        wmma::fragment<wmma::matrix_b, 16, 16, 16, __half, wmma::row_major> b[2];
#pragma unroll
        for (int i = 0; i < 2; i++)
            wmma::load_matrix_sync(a[i], Aef + (wm * 32 + i * 16) * LDA + kk, LDA);
#pragma unroll
        for (int j = 0; j < 2; j++)
            wmma::load_matrix_sync(b[j], Wb + kk * LDB + wn * 32 + j * 16, LDB);
#pragma unroll
        for (int i = 0; i < 2; i++)
#pragma unroll
            for (int j = 0; j < 2; j++)
                wmma::mma_sync(acc[i][j], a[i], b[j], acc[i][j]);
    }
    __syncthreads();  // Aef + Wb reads done -> safe to overwrite with fp32 C

#pragma unroll
    for (int i = 0; i < 2; i++)
#pragma unroll
        for (int j = 0; j < 2; j++)
            wmma::store_matrix_sync(Cs + (wm * 32 + i * 16) * LDC + wn * 32 + j * 16,
                                    acc[i][j], LDC, wmma::mem_row_major);
    __syncthreads();

    // epilogue: thread owns 4 cols x 8 consecutive rows; dsts sorted -> segment accumulate,
    // one Xd load + one red.v4 per segment.
    int c4 = tid & 15;
    int rr = tid >> 4;
    const float4 bv4 = *(const float4*)(bias + cg * 64 + c4 * 4);
    float4 accv = make_float4(0.f, 0.f, 0.f, 0.f);
    float4 xd4 = make_float4(0.f, 0.f, 0.f, 0.f);
    int prev = -1;
#pragma unroll
    for (int it = 0; it < 8; it++) {
        int row = rr * 8 + it;
        int d = s_dst[row];
        if (d < 0) break;
        if (d != prev) {
            if (prev >= 0)
                red_add_v4(out + (size_t)prev * FD + cg * 64 + c4 * 4, accv);
            prev = d;
            accv = make_float4(0.f, 0.f, 0.f, 0.f);
            const __half2* xdp = (const __half2*)(Xd + (size_t)d * FD + cg * 64 + c4 * 4);
            float2 a01 = __half22float2(xdp[0]);
            float2 a23 = __half22float2(xdp[1]);
            xd4 = make_float4(a01.x, a01.y, a23.x, a23.y);
        }
        const __half2* xsp = (const __half2*)(Xs + (size_t)s_src[row] * FD + cg * 64 + c4 * 4);
        float2 s01 = __half22float2(xsp[0]);
        float2 s23 = __half22float2(xsp[1]);
        float4 cv = *(float4*)(Cs + row * LDC + c4 * 4);
        accv.x += gelu_f(cv.x + bv4.x + s01.x + xd4.x);
        accv.y += gelu_f(cv.y + bv4.y + s01.y + xd4.y);
        accv.z += gelu_f(cv.z + bv4.z + s23.x + xd4.z);
        accv.w += gelu_f(cv.w + bv4.w + s23.y + xd4.w);
    }
    if (prev >= 0)
        red_add_v4(out + (size_t)prev * FD + cg * 64 + c4 * 4, accv);
}

// ---------------- launch ----------------
extern "C" void kernel_launch(void* const* d_in, const int* in_sizes, int n_in,
                              void* d_out, int out_size) {
    const float* x    = (const float*)d_in[0];
    const int* ei     = (const int*)d_in[1];   // int32 (JAX x64 disabled)
    const float* ef   = (const float*)d_in[2];
    const float* Wff1 = (const float*)d_in[3];
    const float* bff1 = (const float*)d_in[4];
    const float* Wmp1 = (const float*)d_in[5];
    const float* bmp1 = (const float*)d_in[6];
    const float* Wmp2 = (const float*)d_in[7];
    const float* bmp2 = (const float*)d_in[8];
    const float* Wff2 = (const float*)d_in[9];
    const float* bff2 = (const float*)d_in[10];

    int N = in_sizes[0] / FD;
    int E = in_sizes[1] / 2;

    float* h0;
    __half *h0h, *Xsh, *Xdh, *xh, *efh, *wh;
    int *rowptr, *cnt, *ofs, *srcs, *dsts, *eids;
    cudaGetSymbolAddress((void**)&h0, g_h0);
    cudaGetSymbolAddress((void**)&h0h, g_h0h);
    cudaGetSymbolAddress((void**)&Xsh, g_Xsh);
    cudaGetSymbolAddress((void**)&Xdh, g_Xdh);
    cudaGetSymbolAddress((void**)&xh, g_xh);
    cudaGetSymbolAddress((void**)&efh, g_efh);
    cudaGetSymbolAddress((void**)&wh, g_wh);
    cudaGetSymbolAddress((void**)&rowptr, g_rowptr);
    cudaGetSymbolAddress((void**)&cnt, g_cnt);
    cudaGetSymbolAddress((void**)&ofs, g_ofs);
    cudaGetSymbolAddress((void**)&srcs, g_srcs);
    cudaGetSymbolAddress((void**)&dsts, g_dsts);
    cudaGetSymbolAddress((void**)&eids, g_eids);

    dim3 thr(256);
    int eb = (E + 255) / 256;
    int n4 = N * FD / 4;
    long long tot4 = (long long)N * FD / 4 + (long long)E * EDF / 4 + WTOT / 4 + NN / 4;

    dim3 gN((N + 127) / 128, 4);
    dim3 gN2((N + 127) / 128, 8);
    dim3 gE(4, (E + 127) / 128);

    // 1: convert inputs/weights to fp16 + zero CSR counts
    convert_all<<<(int)((tot4 + 255) / 256), thr>>>(x, ef, Wff1, Wmp1, Wmp2, Wff2,
                                                    xh, efh, wh, (int4*)cnt);
    // 2: CSR histogram
    hist_kernel<<<eb, thr>>>(ei, cnt, E);
    // 3: FFN1 -> h0 (fp32) + h0h (half)
    gemm_node<<<gN, thr>>>(xh, wh + OW1, nullptr, bff1, nullptr, h0, nullptr, h0h, nullptr, N, 1);
    // 4: dual1 (ncu PROBE) -> Xsh, Xdh
    gemm_node<<<gN2, thr>>>(h0h, wh + OM1, wh + OM1 + FD * FD, nullptr, nullptr,
                            nullptr, nullptr, Xsh, Xdh, N, 0);
    // 5-6: finish CSR
    scan_kernel<<<1, 1024>>>(cnt, rowptr, ofs, N);
    scatter_kernel<<<eb, thr>>>(ei, ofs, srcs, dsts, eids, E);
    // 7: edge1: h0 += agg1 (fp32 atomics, in place)
    edge_sorted<<<gE, thr>>>(efh, wh + OM1 + 2 * FD * FD, bmp1, Xsh, Xdh, h0, E);
    // 8: h0 -> h0h
    cvt_h0<<<(n4 + 255) / 256, thr>>>((const float4*)h0, (__half2*)h0h, n4);
    // 9: dual2 -> Xsh, Xdh
    gemm_node<<<gN2, thr>>>(h0h, wh + OM2, wh + OM2 + FD * FD, nullptr, nullptr,
                            nullptr, nullptr, Xsh, Xdh, N, 0);
    // 10: edge2: h0 += agg2 (in place)
    edge_sorted<<<gE, thr>>>(efh, wh + OM2 + 2 * FD * FD, bmp2, Xsh, Xdh, h0, E);
    // 11: h0 -> h0h
    cvt_h0<<<(n4 + 255) / 256, thr>>>((const float4*)h0, (__half2*)h0h, n4);
    // 12: FFN2 + residual -> out
    gemm_node<<<gN, thr>>>(h0h, wh + OW2, nullptr, bff2, x, (float*)d_out, nullptr,
                           nullptr, nullptr, N, 0);
}